// round 14
// baseline (speedup 1.0000x reference)
#include <cuda_runtime.h>

// SparseBiasDiagUnfolder — FINAL (best measured: 6.496 us wall).
// One wave: 146 blocks x 896 threads (28 warps/CTA), 2 window-rows per warp,
// div-free and fully 32-bit index math.
//
//   adj: (B=2, N=2048, N=2048, F=16) fp32; starts 0,4,...,2040 (511);
//   out (B, 511, 56*16).
//
// Structure:
//   * 8176 window rows (b, s, ii); each row = adj[b, 4s+ii, 4s+jj, :] for
//     jj=0..7 -> 512B CONTIGUOUS run. 2 rows per warp -> 4088 warps =
//     146 CTAs x 28 warps exactly (single wave on 148 SMs).
//   * Loads: lane l reads float4 base+l -> 2 independent, fully coalesced
//     512B LDG.128 batched before any store (front-batched MLP).
//   * Stores: per row, the 28 lanes with jj != ii write a contiguous 448B
//     run (diagonal chunk dropped, pos = ii*7 + jj - (jj>ii)); the warp's
//     2 rows target the warp-contiguous output block of its bs group.
//   * Index math: bs = w>>2 < 1022 so b = (bs>=511) — no division; all
//     addresses fit 32-bit (max adj float4 index = 2^25).
//
// Optimization history (wall us): naive gather 6.88 -> one-wave grid 6.56
// -> div-free critical path 6.62 -> 28 warps/CTA + 32-bit addressing 6.50.
// Output-centric and MLP=4 variants are noise-equivalent (6.56-6.66).
// All SOL pipes <10% busy; residual time is graph-replay/launch floor.

namespace {
constexpr int N        = 2048;
constexpr int NSTARTS  = 511;
constexpr int WARPS_PER_BLOCK = 28;
constexpr int THREADS  = WARPS_PER_BLOCK * 32;   // 896
constexpr int BLOCKS   = 146;                    // 4088 warps = 8176 rows / 2
}

__global__ void __launch_bounds__(THREADS)
sparse_diag_unfold_kernel(const float4* __restrict__ adj, float4* __restrict__ out)
{
    const unsigned gt   = blockIdx.x * THREADS + threadIdx.x;
    const unsigned w    = gt >> 5;                 // 0..4087
    const unsigned lane = gt & 31;

    const unsigned bs      = w >> 2;               // b*511 + s, < 1022
    const unsigned ii_base = (w & 3) * 2;          // 0,2,4,6

    const unsigned b = (bs >= NSTARTS);            // no division
    const unsigned s = bs - b * NSTARTS;

    // 32-bit float4 base index of row (bs, ii_base):
    //   b*N*N*4 + s*(N+1)*16 + ii_base*N*4 + lane   (max ~2^25)
    const unsigned base0 = b * (N * N * 4u)
                         + s * ((N + 1) * 16u)
                         + ii_base * (N * 4u)
                         + lane;

    const unsigned jj = lane >> 2;
    const unsigned v  = lane & 3;

    // 2 independent coalesced 512B loads, batched (front-batched MLP).
    float4 vals[2];
    #pragma unroll
    for (int k = 0; k < 2; k++)
        vals[k] = adj[base0 + (unsigned)k * (N * 4u)];

    const unsigned out_base = bs * (56u * 4u);
    #pragma unroll
    for (int k = 0; k < 2; k++) {
        const unsigned ii = ii_base + k;
        if (jj != ii) {
            const unsigned pos = ii * 7u + jj - (jj > ii);   // 0..55
            out[out_base + pos * 4u + v] = vals[k];
        }
    }
}

extern "C" void kernel_launch(void* const* d_in, const int* in_sizes, int n_in,
                              void* d_out, int out_size)
{
    const float4* adj = (const float4*)d_in[0];
    float4* out = (float4*)d_out;
    sparse_diag_unfold_kernel<<<BLOCKS, THREADS>>>(adj, out);
}

// round 15
// speedup vs baseline: 1.0337x; 1.0337x over previous
#include <cuda_runtime.h>

// SparseBiasDiagUnfolder — dense variant: 73 blocks x 896 threads
// (28 warps/CTA), 4 window-rows per warp (MLP_p1 = 4), one wave,
// div-free fully 32-bit index math.
//
//   adj: (B=2, N=2048, N=2048, F=16) fp32; starts 0,4,...,2040 (511);
//   out (B, 511, 56*16).
//
// 8176 rows, 4 per warp -> 2044 warps = 73 CTAs x 28 warps exactly.
// 112 independent coalesced 512B loads in flight per SM (28 warps x 4),
// maximizing per-SM latency hiding; only 73 SMs used (latency-bound at
// 7% DRAM, so aggregate bandwidth is not the constraint).
// Warp w covers rows [4w, 4w+4); all share bs = w>>1 (b*511+s, bs<1022 so
// b = bs>=511 — no division). Stores: 28 active lanes/row, contiguous
// 448B run; the warp's 4 rows write one contiguous 1792B output block.

namespace {
constexpr int N        = 2048;
constexpr int NSTARTS  = 511;
constexpr int WARPS_PER_BLOCK = 28;
constexpr int THREADS  = WARPS_PER_BLOCK * 32;   // 896
constexpr int BLOCKS   = 73;                     // 2044 warps = 8176 rows / 4
}

__global__ void __launch_bounds__(THREADS)
sparse_diag_unfold_kernel(const float4* __restrict__ adj, float4* __restrict__ out)
{
    const unsigned gt   = blockIdx.x * THREADS + threadIdx.x;
    const unsigned w    = gt >> 5;                 // 0..2043
    const unsigned lane = gt & 31;

    const unsigned bs      = w >> 1;               // b*511 + s, < 1022
    const unsigned ii_base = (w & 1) * 4;          // 0 or 4

    const unsigned b = (bs >= NSTARTS);            // no division
    const unsigned s = bs - b * NSTARTS;

    // 32-bit float4 base index of row (bs, ii_base)  (max ~2^25)
    const unsigned base0 = b * (N * N * 4u)
                         + s * ((N + 1) * 16u)
                         + ii_base * (N * 4u)
                         + lane;

    const unsigned jj = lane >> 2;
    const unsigned v  = lane & 3;

    // 4 independent coalesced 512B loads, batched (MLP_p1 = 4).
    float4 vals[4];
    #pragma unroll
    for (int k = 0; k < 4; k++)
        vals[k] = adj[base0 + (unsigned)k * (N * 4u)];

    const unsigned out_base = bs * (56u * 4u);
    #pragma unroll
    for (int k = 0; k < 4; k++) {
        const unsigned ii = ii_base + k;
        if (jj != ii) {
            const unsigned pos = ii * 7u + jj - (jj > ii);   // 0..55
            out[out_base + pos * 4u + v] = vals[k];
        }
    }
}

extern "C" void kernel_launch(void* const* d_in, const int* in_sizes, int n_in,
                              void* d_out, int out_size)
{
    const float4* adj = (const float4*)d_in[0];
    float4* out = (float4*)d_out;
    sparse_diag_unfold_kernel<<<BLOCKS, THREADS>>>(adj, out);
}

// round 16
// speedup vs baseline: 1.0386x; 1.0048x over previous
#include <cuda_runtime.h>

// SparseBiasDiagUnfolder — FINAL kernel (best measured wall: 6.496 us).
// One wave: 146 blocks x 896 threads (28 warps/CTA), 2 window-rows per warp,
// div-free and fully 32-bit index math.
//
//   adj: (B=2, N=2048, N=2048, F=16) fp32; starts 0,4,...,2040 (511);
//   out (B, 511, 56*16).
//
// Structure:
//   * 8176 window rows (b, s, ii); row = adj[b, 4s+ii, 4s+jj, :], jj=0..7
//     -> one 512B CONTIGUOUS run per row. 2 rows/warp -> 4088 warps =
//     146 CTAs x 28 warps exactly (single wave on 148 SMs).
//   * Loads: lane l reads float4 base+l -> 2 independent fully-coalesced
//     512B LDG.128 batched before any store.
//   * Stores: per row, 28 lanes (jj != ii) write a contiguous 448B run
//     (diagonal chunk dropped, pos = ii*7 + jj - (jj>ii)).
//   * Index math: bs = w>>2 < 1022 so b = (bs>=511) — no division; all
//     addresses fit 32-bit (max adj float4 index = 2^25).
//
// Tuning summary (16 benches): one-wave grid was the only significant win
// (6.88 -> ~6.5); rows/warp {1,2,4}, warps/CTA {8,14,28}, input- vs
// output-centric decompositions are all noise-equivalent (6.50-6.88 band;
// identical source printed 6.496/6.656/6.880 across runs). All SOL pipes
// <11% busy; the residual wall time is graph-replay/launch floor.

namespace {
constexpr int N        = 2048;
constexpr int NSTARTS  = 511;
constexpr int WARPS_PER_BLOCK = 28;
constexpr int THREADS  = WARPS_PER_BLOCK * 32;   // 896
constexpr int BLOCKS   = 146;                    // 4088 warps = 8176 rows / 2
}

__global__ void __launch_bounds__(THREADS)
sparse_diag_unfold_kernel(const float4* __restrict__ adj, float4* __restrict__ out)
{
    const unsigned gt   = blockIdx.x * THREADS + threadIdx.x;
    const unsigned w    = gt >> 5;                 // 0..4087
    const unsigned lane = gt & 31;

    const unsigned bs      = w >> 2;               // b*511 + s, < 1022
    const unsigned ii_base = (w & 3) * 2;          // 0,2,4,6

    const unsigned b = (bs >= NSTARTS);            // no division
    const unsigned s = bs - b * NSTARTS;

    // 32-bit float4 base index of row (bs, ii_base):
    //   b*N*N*4 + s*(N+1)*16 + ii_base*N*4 + lane   (max ~2^25)
    const unsigned base0 = b * (N * N * 4u)
                         + s * ((N + 1) * 16u)
                         + ii_base * (N * 4u)
                         + lane;

    const unsigned jj = lane >> 2;
    const unsigned v  = lane & 3;

    // 2 independent coalesced 512B loads, batched (front-batched MLP).
    float4 vals[2];
    #pragma unroll
    for (int k = 0; k < 2; k++)
        vals[k] = adj[base0 + (unsigned)k * (N * 4u)];

    const unsigned out_base = bs * (56u * 4u);
    #pragma unroll
    for (int k = 0; k < 2; k++) {
        const unsigned ii = ii_base + k;
        if (jj != ii) {
            const unsigned pos = ii * 7u + jj - (jj > ii);   // 0..55
            out[out_base + pos * 4u + v] = vals[k];
        }
    }
}

extern "C" void kernel_launch(void* const* d_in, const int* in_sizes, int n_in,
                              void* d_out, int out_size)
{
    const float4* adj = (const float4*)d_in[0];
    float4* out = (float4*)d_out;
    sparse_diag_unfold_kernel<<<BLOCKS, THREADS>>>(adj, out);
}